// round 3
// baseline (speedup 1.0000x reference)
#include <cuda_runtime.h>
#include <math.h>
#include <stdint.h>

// Problem dims (fixed by the dataset)
#define BB 4
#define LL 2048
#define DD 2048
#define RR 2560
#define MM (BB * LL)   // 8192

// ---------------------------------------------------------------------------
// Device scratch (static __device__ arrays: allocation-free per harness rules)
// ---------------------------------------------------------------------------
__device__ float g_Wc[4u * RR * RR];  // conv_w transposed -> [k][o][i]
__device__ float g_H1[(size_t)MM * RR];  // silu(x@w1^T+b1); later reused for scan output h
__device__ float g_HC[(size_t)MM * RR];  // conv output
__device__ float g_Rl[(size_t)MM * RR];  // r_lin, then 'a' (in place)
__device__ float g_Il[(size_t)MM * RR];  // i_lin, then 'b' (in place)
__device__ float g_sp[RR];               // -8 * softplus(lam)

// ---------------------------------------------------------------------------
// Tiled TN SGEMM: C[M,N] = A[M,K] @ W[N,K]^T (+bias) (+=C) (SiLU)
// A rows optionally time-shifted within each batch (zero outside [0,L)).
// Block tile 128x128, K-tile 16, 256 threads, 8x8 per-thread microtile,
// register-prefetch pipelining of global loads.
// ---------------------------------------------------------------------------
#define TBM 128
#define TBN 128
#define TBK 16

template<int EPI, bool ACC, bool BIAS, bool SHIFT>
__global__ __launch_bounds__(256, 2)
void gemm_tn(const float* __restrict__ A, const float* __restrict__ W,
             const float* __restrict__ bias, float* __restrict__ C,
             int N, int K, int shift)
{
    __shared__ float As[TBK][TBM + 4];
    __shared__ float Bs[TBK][TBN + 4];

    const int tid = threadIdx.x;
    const int bm = blockIdx.y * TBM;
    const int bn = blockIdx.x * TBN;

    const int tx = tid & 15;   // n sub-tile
    const int ty = tid >> 4;   // m sub-tile

    // Global-load mapping: element e = tid + i*256 -> row = e>>2, kvec=(e&3)*4
    const int kq   = (tid & 3) << 2;
    const int rowL = tid >> 2;           // 0..63 (second load adds 64)

    const float* Aptr[2];
    bool aval[2];
#pragma unroll
    for (int i = 0; i < 2; i++) {
        int row = rowL + i * 64;
        int m = bm + row;
        int arow = m;
        bool v = true;
        if (SHIFT) {
            int t = m & (LL - 1);
            int ts = t + shift;
            v = ((unsigned)ts < (unsigned)LL);
            arow = (m - t) + (v ? ts : 0);
        }
        aval[i] = v;
        Aptr[i] = A + (size_t)arow * K + kq;
    }
    const float* Wptr[2];
#pragma unroll
    for (int i = 0; i < 2; i++) {
        int row = rowL + i * 64;
        Wptr[i] = W + (size_t)(bn + row) * K + kq;
    }

    float acc[8][8];
#pragma unroll
    for (int i = 0; i < 8; i++)
#pragma unroll
        for (int j = 0; j < 8; j++) acc[i][j] = 0.f;

    float4 pa[2], pb[2];
#pragma unroll
    for (int i = 0; i < 2; i++) {
        pa[i] = aval[i] ? *(const float4*)(Aptr[i]) : make_float4(0.f, 0.f, 0.f, 0.f);
        pb[i] = *(const float4*)(Wptr[i]);
    }

    const int KT = K / TBK;
    for (int kt = 0; kt < KT; kt++) {
        // stage current registers into smem (transposed: [k][m])
#pragma unroll
        for (int i = 0; i < 2; i++) {
            int row = rowL + i * 64;
            As[kq + 0][row] = pa[i].x;
            As[kq + 1][row] = pa[i].y;
            As[kq + 2][row] = pa[i].z;
            As[kq + 3][row] = pa[i].w;
            Bs[kq + 0][row] = pb[i].x;
            Bs[kq + 1][row] = pb[i].y;
            Bs[kq + 2][row] = pb[i].z;
            Bs[kq + 3][row] = pb[i].w;
        }
        __syncthreads();

        // prefetch next K-tile from global while computing this one
        if (kt + 1 < KT) {
            int off = (kt + 1) * TBK;
#pragma unroll
            for (int i = 0; i < 2; i++) {
                pa[i] = aval[i] ? *(const float4*)(Aptr[i] + off)
                                : make_float4(0.f, 0.f, 0.f, 0.f);
                pb[i] = *(const float4*)(Wptr[i] + off);
            }
        }

#pragma unroll
        for (int k = 0; k < TBK; k++) {
            float av[8], bv[8];
            *(float4*)&av[0] = *(const float4*)&As[k][ty * 8];
            *(float4*)&av[4] = *(const float4*)&As[k][ty * 8 + 4];
            *(float4*)&bv[0] = *(const float4*)&Bs[k][tx * 8];
            *(float4*)&bv[4] = *(const float4*)&Bs[k][tx * 8 + 4];
#pragma unroll
            for (int i = 0; i < 8; i++)
#pragma unroll
                for (int j = 0; j < 8; j++)
                    acc[i][j] = fmaf(av[i], bv[j], acc[i][j]);
        }
        __syncthreads();
    }

    // Epilogue
    float bb[8];
    if (BIAS) {
#pragma unroll
        for (int j = 0; j < 8; j++) bb[j] = bias[bn + tx * 8 + j];
    }
#pragma unroll
    for (int i = 0; i < 8; i++) {
        int m = bm + ty * 8 + i;
        float* crow = C + (size_t)m * N + bn + tx * 8;
        float v[8];
        if (ACC) {
            float4 c0 = *(const float4*)crow;
            float4 c1 = *(const float4*)(crow + 4);
            v[0] = c0.x; v[1] = c0.y; v[2] = c0.z; v[3] = c0.w;
            v[4] = c1.x; v[5] = c1.y; v[6] = c1.z; v[7] = c1.w;
        } else {
#pragma unroll
            for (int j = 0; j < 8; j++) v[j] = 0.f;
        }
#pragma unroll
        for (int j = 0; j < 8; j++) {
            float z = acc[i][j];
            if (BIAS) z += bb[j];
            if (EPI == 1) z = z / (1.f + expf(-z));  // SiLU
            v[j] += z;
        }
        *(float4*)crow = make_float4(v[0], v[1], v[2], v[3]);
        *(float4*)(crow + 4) = make_float4(v[4], v[5], v[6], v[7]);
    }
}

// ---------------------------------------------------------------------------
// conv_w [o][i][k] -> Wc [k][o][i]  (coalesced writes)
// ---------------------------------------------------------------------------
__global__ void transpose_convw(const float* __restrict__ cw, float* __restrict__ wc)
{
    int idx = blockIdx.x * blockDim.x + threadIdx.x;  // exact multiple of 256
    int k = idx / (RR * RR);
    int rem = idx - k * (RR * RR);
    int o = rem / RR;
    int i = rem - o * RR;
    wc[idx] = cw[((size_t)o * RR + i) * 4 + k];
}

// -8 * softplus(lam)
__global__ void prep_sp(const float* __restrict__ lam, float* __restrict__ sp)
{
    int d = blockIdx.x * blockDim.x + threadIdx.x;
    if (d < RR) {
        float l = lam[d];
        float s = (l > 20.f) ? l : log1pf(expf(l));
        sp[d] = -8.f * s;
    }
}

// gates: rl <- a = exp(sp[d]*sigmoid(rl));  il <- b = sqrt(1-a^2)*sigmoid(il)*hc
__global__ void gate_kernel(float* __restrict__ rl, float* __restrict__ il,
                            const float* __restrict__ hc, const float* __restrict__ sp)
{
    int idx = blockIdx.x * blockDim.x + threadIdx.x;  // exact multiple of 256
    int d = idx % RR;
    float r  = 1.f / (1.f + expf(-rl[idx]));
    float ig = 1.f / (1.f + expf(-il[idx]));
    float la = sp[d] * r;          // = -8 * r * softplus(lam)
    float a  = expf(la);
    float mult = sqrtf(fmaxf(1.f - a * a, 0.f));
    rl[idx] = a;
    il[idx] = mult * ig * hc[idx];
}

// sequential linear recurrence h_t = a_t*h_{t-1} + b_t, per (batch, channel)
__global__ void scan_kernel(const float* __restrict__ a, const float* __restrict__ bv,
                            float* __restrict__ h)
{
    int gid = blockIdx.x * blockDim.x + threadIdx.x;
    if (gid >= BB * RR) return;
    int b = gid / RR;
    int d = gid - b * RR;
    size_t base = (size_t)b * LL * RR + d;
    float hp = 0.f;
#pragma unroll 4
    for (int t = 0; t < LL; t++) {
        size_t off = base + (size_t)t * RR;
        hp = fmaf(a[off], hp, bv[off]);
        h[off] = hp;
    }
}

// ---------------------------------------------------------------------------
extern "C" void kernel_launch(void* const* d_in, const int* in_sizes, int n_in,
                              void* d_out, int out_size)
{
    const float* x      = (const float*)d_in[0];
    const float* w1     = (const float*)d_in[1];
    const float* b1     = (const float*)d_in[2];
    const float* conv_w = (const float*)d_in[3];
    const float* conv_b = (const float*)d_in[4];
    const float* wa     = (const float*)d_in[5];
    const float* ba     = (const float*)d_in[6];
    const float* wx     = (const float*)d_in[7];
    const float* bx     = (const float*)d_in[8];
    const float* lam    = (const float*)d_in[9];
    const float* w2     = (const float*)d_in[10];
    const float* b2     = (const float*)d_in[11];
    float* out = (float*)d_out;

    float *Wc, *H1, *HC, *Rl, *Il, *sp;
    cudaGetSymbolAddress((void**)&Wc, g_Wc);
    cudaGetSymbolAddress((void**)&H1, g_H1);
    cudaGetSymbolAddress((void**)&HC, g_HC);
    cudaGetSymbolAddress((void**)&Rl, g_Rl);
    cudaGetSymbolAddress((void**)&Il, g_Il);
    cudaGetSymbolAddress((void**)&sp, g_sp);

    // prep: weight transpose + softplus table
    transpose_convw<<<(4u * RR * RR) / 256, 256>>>(conv_w, Wc);
    prep_sp<<<(RR + 255) / 256, 256>>>(lam, sp);

    dim3 blk(256);
    dim3 g1(RR / TBN, MM / TBM);   // N=2560 GEMMs
    dim3 g2(DD / TBN, MM / TBM);   // N=2048 GEMM

    // 1) H1 = silu(x @ w1^T + b1)
    gemm_tn<1, false, true,  false><<<g1, blk>>>(x,  w1, b1, H1, RR, DD, 0);

    // 2) HC = sum_k shift(H1, 2k-3) @ Wc[k]^T + conv_b
    gemm_tn<0, false, true,  true ><<<g1, blk>>>(H1, Wc + 0 * (size_t)RR * RR, conv_b, HC, RR, RR, -3);
    gemm_tn<0, true,  false, true ><<<g1, blk>>>(H1, Wc + 1 * (size_t)RR * RR, nullptr, HC, RR, RR, -1);
    gemm_tn<0, true,  false, true ><<<g1, blk>>>(H1, Wc + 2 * (size_t)RR * RR, nullptr, HC, RR, RR,  1);
    gemm_tn<0, true,  false, true ><<<g1, blk>>>(H1, Wc + 3 * (size_t)RR * RR, nullptr, HC, RR, RR,  3);

    // 3) gate pre-activations
    gemm_tn<0, false, true,  false><<<g1, blk>>>(HC, wa, ba, Rl, RR, RR, 0);
    gemm_tn<0, false, true,  false><<<g1, blk>>>(HC, wx, bx, Il, RR, RR, 0);

    // 4) a/b for the RG-LRU (in place into Rl/Il)
    gate_kernel<<<((size_t)MM * RR) / 256, 256>>>(Rl, Il, HC, sp);

    // 5) linear recurrence -> h (reuse H1)
    scan_kernel<<<(BB * RR + 63) / 64, 64>>>(Rl, Il, H1);

    // 6) out = h @ w2^T + b2
    gemm_tn<0, false, true,  false><<<g2, blk>>>(H1, w2, b2, out, DD, RR, 0);
}

// round 4
// speedup vs baseline: 5.3280x; 5.3280x over previous
#include <cuda_runtime.h>
#include <math.h>
#include <stdint.h>

// Problem dims (fixed by the dataset)
#define BB 4
#define LL 2048
#define DD 2048
#define RR 2560
#define MM (BB * LL)      // 8192
#define K4 (4 * RR)       // 10240 (conv fused-K)

// ---------------------------------------------------------------------------
// Device scratch (static __device__ arrays: allocation-free per harness rules)
// ---------------------------------------------------------------------------
__device__ float g_W1r[(size_t)RR * DD];      // tf32-rounded w1
__device__ float g_Wg [(size_t)2 * RR * RR];  // tf32-rounded [wa ; wx]
__device__ float g_W2r[(size_t)DD * RR];      // tf32-rounded w2
__device__ float g_Wc2[(size_t)RR * K4];      // conv_w packed [o][t*R+i], rounded
__device__ float g_Xr [(size_t)MM * DD];      // tf32-rounded x
__device__ float g_H1 [(size_t)MM * RR];      // silu(x@w1^T+b1) rounded; reused for scan out h
__device__ float g_HC [(size_t)MM * RR];      // conv output (rounded)
__device__ float g_G  [(size_t)MM * 2 * RR];  // [r_lin | i_lin] gate pre-activations
__device__ float g_Ga [(size_t)MM * RR];      // a
__device__ float g_Gb [(size_t)MM * RR];      // b
__device__ float g_sp [RR];                   // -8 * softplus(lam)

// ---------------------------------------------------------------------------
// helpers
// ---------------------------------------------------------------------------
__device__ __forceinline__ float tf32r(float x) {
    uint32_t u;
    asm("cvt.rna.tf32.f32 %0, %1;" : "=r"(u) : "f"(x));
    return __uint_as_float(u);
}

__device__ __forceinline__ void cpa16(uint32_t dst, const void* src, int sz) {
    asm volatile("cp.async.cg.shared.global [%0], [%1], 16, %2;\n"
                 :: "r"(dst), "l"(src), "r"(sz));
}

__device__ __forceinline__ void mma_tf32(float* c, const uint32_t* a, const uint32_t* b) {
    asm volatile(
        "mma.sync.aligned.m16n8k8.row.col.f32.tf32.tf32.f32 "
        "{%0,%1,%2,%3}, {%4,%5,%6,%7}, {%8,%9}, {%0,%1,%2,%3};\n"
        : "+f"(c[0]), "+f"(c[1]), "+f"(c[2]), "+f"(c[3])
        : "r"(a[0]), "r"(a[1]), "r"(a[2]), "r"(a[3]), "r"(b[0]), "r"(b[1]));
}

// ---------------------------------------------------------------------------
// tf32 tensor-core TN GEMM: C[M,N] = A[M,K] @ W[N,K]^T (+bias)(epilogue)
// Block 128x128x32, 256 threads (8 warps as 2x4), warp tile 64x32,
// 4x4 m16n8k8 tiles per warp, cp.async double-buffered.
// CONV: A is a 4-tap time-shifted view of H1 (K = 4*RR, lda = RR);
//       tap = k0/RR, shift = 2*tap-3, rows outside [0,L) zero-filled.
// EPI: 0 = none, 1 = SiLU + tf32-round, 2 = tf32-round.
// ---------------------------------------------------------------------------
#define LDS_ 36
#define SMEM_BYTES (2 * (128 * LDS_ + 128 * LDS_) * 4)   // 73728

template<int EPI, bool BIAS, bool CONV>
__global__ __launch_bounds__(256, 2)
void gemm_mma(const float* __restrict__ A, const float* __restrict__ W,
              const float* __restrict__ bias, float* __restrict__ C,
              int N, int K, int lda)
{
    extern __shared__ float sm[];
    const int tid  = threadIdx.x;
    const int lane = tid & 31;
    const int wid  = tid >> 5;
    const int g    = lane >> 2;      // group id (row within mma frag)
    const int tq   = lane & 3;       // thread-in-group (k within frag)
    const int wm   = (wid >> 2) << 6;  // warp m offset (0 or 64)
    const int wn   = (wid & 3) << 5;   // warp n offset (0,32,64,96)
    const int bm   = blockIdx.y * 128;
    const int bn   = blockIdx.x * 128;

    const int lrow = tid >> 3;         // loader row 0..31 (+32*i)
    const int lkq  = (tid & 7) << 2;   // loader k 0..28

    const uint32_t smbase = (uint32_t)__cvta_generic_to_shared(sm);

    float acc[4][4][4];
#pragma unroll
    for (int a0 = 0; a0 < 4; a0++)
#pragma unroll
        for (int b0 = 0; b0 < 4; b0++)
#pragma unroll
            for (int c0 = 0; c0 < 4; c0++) acc[a0][b0][c0] = 0.f;

    const int KT = K / 32;

    auto issue = [&](int kt, int st) {
        const int k0 = kt * 32;
        // B tile: W rows [bn, bn+128), cols [k0, k0+32)
        uint32_t bdst = smbase + (uint32_t)((2 * 128 * LDS_ + st * 128 * LDS_
                                             + lrow * LDS_ + lkq) * 4);
        const float* bsrc = W + (size_t)(bn + lrow) * K + k0 + lkq;
#pragma unroll
        for (int i = 0; i < 4; i++)
            cpa16(bdst + (uint32_t)(i * 32 * LDS_ * 4), bsrc + (size_t)32 * i * K, 16);
        // A tile
        int tap = 0, shift = 0, kcol = k0;
        if (CONV) { tap = k0 / RR; kcol = k0 - tap * RR; shift = 2 * tap - 3; }
        uint32_t adst = smbase + (uint32_t)((st * 128 * LDS_ + lrow * LDS_ + lkq) * 4);
#pragma unroll
        for (int i = 0; i < 4; i++) {
            int m = bm + lrow + 32 * i;
            int arow = m, sz = 16;
            if (CONV) {
                int t  = m & (LL - 1);
                int ts = t + shift;
                if ((unsigned)ts < (unsigned)LL) arow = m - t + ts;
                else                             sz = 0;   // zero-fill pad row
            }
            cpa16(adst + (uint32_t)(i * 32 * LDS_ * 4),
                  A + (size_t)arow * lda + kcol + lkq, sz);
        }
        asm volatile("cp.async.commit_group;\n");
    };

    issue(0, 0);
    for (int kt = 0; kt < KT; kt++) {
        const int st = kt & 1;
        if (kt + 1 < KT) {
            issue(kt + 1, st ^ 1);
            asm volatile("cp.async.wait_group 1;\n");
        } else {
            asm volatile("cp.async.wait_group 0;\n");
        }
        __syncthreads();

        const float* As = sm + st * 128 * LDS_;
        const float* Bs = sm + 2 * 128 * LDS_ + st * 128 * LDS_;

#pragma unroll
        for (int s8 = 0; s8 < 4; s8++) {
            const int kk = s8 * 8 + tq;
            uint32_t af[4][4], bf[4][2];
#pragma unroll
            for (int nt = 0; nt < 4; nt++) {
                const float* bp = Bs + (wn + nt * 8 + g) * LDS_ + kk;
                bf[nt][0] = __float_as_uint(bp[0]);
                bf[nt][1] = __float_as_uint(bp[4]);
            }
#pragma unroll
            for (int mt = 0; mt < 4; mt++) {
                const float* ap = As + (wm + mt * 16 + g) * LDS_ + kk;
                af[mt][0] = __float_as_uint(ap[0]);
                af[mt][1] = __float_as_uint(ap[8 * LDS_]);
                af[mt][2] = __float_as_uint(ap[4]);
                af[mt][3] = __float_as_uint(ap[8 * LDS_ + 4]);
            }
#pragma unroll
            for (int mt = 0; mt < 4; mt++)
#pragma unroll
                for (int nt = 0; nt < 4; nt++)
                    mma_tf32(acc[mt][nt], af[mt], bf[nt]);
        }
        __syncthreads();
    }

    // Epilogue. c0,c1 -> (row, col..col+1); c2,c3 -> (row+8, col..col+1)
#pragma unroll
    for (int mt = 0; mt < 4; mt++) {
        const int r0 = bm + wm + mt * 16 + g;
#pragma unroll
        for (int nt = 0; nt < 4; nt++) {
            const int col = bn + wn + nt * 8 + tq * 2;
            float bx_ = 0.f, by_ = 0.f;
            if (BIAS) { float2 bb = *(const float2*)(bias + col); bx_ = bb.x; by_ = bb.y; }
            float v[4] = { acc[mt][nt][0] + bx_, acc[mt][nt][1] + by_,
                           acc[mt][nt][2] + bx_, acc[mt][nt][3] + by_ };
            if (EPI == 1) {
#pragma unroll
                for (int j = 0; j < 4; j++) {
                    float z = v[j];
                    z = z / (1.f + __expf(-z));   // SiLU
                    v[j] = tf32r(z);
                }
            } else if (EPI == 2) {
#pragma unroll
                for (int j = 0; j < 4; j++) v[j] = tf32r(v[j]);
            }
            *(float2*)(C + (size_t)r0 * N + col)       = make_float2(v[0], v[1]);
            *(float2*)(C + (size_t)(r0 + 8) * N + col) = make_float2(v[2], v[3]);
        }
    }
}

// ---------------------------------------------------------------------------
// prep kernels
// ---------------------------------------------------------------------------
__global__ void round_copy(const float* __restrict__ in, float* __restrict__ out, int n)
{
    int i = blockIdx.x * 256 + threadIdx.x;
    if (i < n) out[i] = tf32r(in[i]);
}

// conv_w [o][i][t] -> Wc2 [o][t*R + i], tf32-rounded
__global__ void conv_pack(const float* __restrict__ cw, float* __restrict__ wc2)
{
    int idx = blockIdx.x * 256 + threadIdx.x;      // exact multiple of 256
    int o   = idx / K4;
    int rem = idx - o * K4;
    int t   = rem / RR;
    int i   = rem - t * RR;
    wc2[idx] = tf32r(cw[((size_t)o * RR + i) * 4 + t]);
}

__global__ void prep_sp(const float* __restrict__ lam, float* __restrict__ sp)
{
    int d = blockIdx.x * 256 + threadIdx.x;
    if (d < RR) {
        float l = lam[d];
        float s = (l > 20.f) ? l : log1pf(expf(l));
        sp[d] = -8.f * s;
    }
}

// gates from packed pre-activations G = [r_lin | i_lin] (bias added here)
__global__ void gate2(const float* __restrict__ G, const float* __restrict__ hc,
                      const float* __restrict__ ba, const float* __restrict__ bx,
                      const float* __restrict__ sp,
                      float* __restrict__ av, float* __restrict__ bv)
{
    int idx = blockIdx.x * 256 + threadIdx.x;   // exact multiple of 256
    int m = idx / RR;
    int d = idx - m * RR;
    float rl = G[(size_t)m * (2 * RR) + d]       + ba[d];
    float il = G[(size_t)m * (2 * RR) + RR + d]  + bx[d];
    float r  = 1.f / (1.f + __expf(-rl));
    float ig = 1.f / (1.f + __expf(-il));
    float a  = __expf(sp[d] * r);
    float mult = sqrtf(fmaxf(1.f - a * a, 0.f));
    av[idx] = a;
    bv[idx] = mult * ig * hc[idx];
}

// sequential recurrence h_t = a_t*h_{t-1} + b_t; h stored tf32-rounded
__global__ void scan_kernel(const float* __restrict__ a, const float* __restrict__ bv,
                            float* __restrict__ h)
{
    int gid = blockIdx.x * blockDim.x + threadIdx.x;
    if (gid >= BB * RR) return;
    int b = gid / RR;
    int d = gid - b * RR;
    size_t base = (size_t)b * LL * RR + d;
    float hp = 0.f;
#pragma unroll 4
    for (int t = 0; t < LL; t++) {
        size_t off = base + (size_t)t * RR;
        hp = fmaf(a[off], hp, bv[off]);
        h[off] = tf32r(hp);
    }
}

// ---------------------------------------------------------------------------
extern "C" void kernel_launch(void* const* d_in, const int* in_sizes, int n_in,
                              void* d_out, int out_size)
{
    const float* x      = (const float*)d_in[0];
    const float* w1     = (const float*)d_in[1];
    const float* b1     = (const float*)d_in[2];
    const float* conv_w = (const float*)d_in[3];
    const float* conv_b = (const float*)d_in[4];
    const float* wa     = (const float*)d_in[5];
    const float* ba     = (const float*)d_in[6];
    const float* wx     = (const float*)d_in[7];
    const float* bx     = (const float*)d_in[8];
    const float* lam    = (const float*)d_in[9];
    const float* w2     = (const float*)d_in[10];
    const float* b2     = (const float*)d_in[11];
    float* out = (float*)d_out;

    float *W1r, *Wg, *W2r, *Wc2, *Xr, *H1, *HC, *G, *Ga, *Gb, *sp;
    cudaGetSymbolAddress((void**)&W1r, g_W1r);
    cudaGetSymbolAddress((void**)&Wg,  g_Wg);
    cudaGetSymbolAddress((void**)&W2r, g_W2r);
    cudaGetSymbolAddress((void**)&Wc2, g_Wc2);
    cudaGetSymbolAddress((void**)&Xr,  g_Xr);
    cudaGetSymbolAddress((void**)&H1,  g_H1);
    cudaGetSymbolAddress((void**)&HC,  g_HC);
    cudaGetSymbolAddress((void**)&G,   g_G);
    cudaGetSymbolAddress((void**)&Ga,  g_Ga);
    cudaGetSymbolAddress((void**)&Gb,  g_Gb);
    cudaGetSymbolAddress((void**)&sp,  g_sp);

    // opt-in to >48KB dynamic smem (idempotent; immediate API, capture-safe)
    cudaFuncSetAttribute(gemm_mma<1, true,  false>, cudaFuncAttributeMaxDynamicSharedMemorySize, SMEM_BYTES);
    cudaFuncSetAttribute(gemm_mma<2, true,  true >, cudaFuncAttributeMaxDynamicSharedMemorySize, SMEM_BYTES);
    cudaFuncSetAttribute(gemm_mma<0, false, false>, cudaFuncAttributeMaxDynamicSharedMemorySize, SMEM_BYTES);
    cudaFuncSetAttribute(gemm_mma<0, true,  false>, cudaFuncAttributeMaxDynamicSharedMemorySize, SMEM_BYTES);

    // ---- prep: RN-round every MMA input once ----
    round_copy<<<(RR * DD + 255) / 256, 256>>>(w1, W1r, RR * DD);
    round_copy<<<(RR * RR + 255) / 256, 256>>>(wa, Wg,           RR * RR);
    round_copy<<<(RR * RR + 255) / 256, 256>>>(wx, Wg + (size_t)RR * RR, RR * RR);
    round_copy<<<(DD * RR + 255) / 256, 256>>>(w2, W2r, DD * RR);
    round_copy<<<(MM * DD + 255) / 256, 256>>>(x,  Xr,  MM * DD);
    conv_pack<<<((size_t)RR * K4) / 256, 256>>>(conv_w, Wc2);
    prep_sp<<<(RR + 255) / 256, 256>>>(lam, sp);

    dim3 blk(256);
    dim3 gN2560(RR / 128,        MM / 128);   // 20 x 64
    dim3 gN5120(2 * RR / 128,    MM / 128);   // 40 x 64
    dim3 gN2048(DD / 128,        MM / 128);   // 16 x 64

    // 1) H1 = tf32( silu(x @ w1^T + b1) )
    gemm_mma<1, true,  false><<<gN2560, blk, SMEM_BYTES>>>(Xr, W1r, b1, H1, RR, DD, DD);
    // 2) HC = tf32( conv(H1) + conv_b )   — single fused GEMM, K = 4*R
    gemm_mma<2, true,  true ><<<gN2560, blk, SMEM_BYTES>>>(H1, Wc2, conv_b, HC, RR, K4, RR);
    // 3) G = HC @ [wa;wx]^T   (biases added in gate2)
    gemm_mma<0, false, false><<<gN5120, blk, SMEM_BYTES>>>(HC, Wg, nullptr, G, 2 * RR, RR, RR);
    // 4) a/b for RG-LRU
    gate2<<<((size_t)MM * RR) / 256, 256>>>(G, HC, ba, bx, sp, Ga, Gb);
    // 5) linear recurrence -> h (tf32-rounded, into H1)
    scan_kernel<<<(BB * RR + 63) / 64, 64>>>(Ga, Gb, H1);
    // 6) out = h @ w2^T + b2
    gemm_mma<0, true,  false><<<gN2048, blk, SMEM_BYTES>>>(H1, W2r, b2, out, DD, RR, RR);
}